// round 1
// baseline (speedup 1.0000x reference)
#include <cuda_runtime.h>

// DilateAttention: B=8, C=384 (12 heads x 32), H=W=56, kernel 3x3, dilation 2, pad 2.
// q,k,v: [B, C, H, W] float32 (C-major, HW contiguous). out: [B, H, W, C] float32.
// Per (b, head, y, x): logits_p = (q . k_p) * 32^-0.5 for 9 dilated neighbors
// (zero-padded OOB -> logit exactly 0, still included in softmax denominator),
// softmax over 9, out = sum_p w_p * v_p.

#define HD    32
#define HEADS 12
#define WD    56
#define HT    56
#define BD    8
#define HW    (WD * HT)
#define CTOT  (HEADS * HD)

__global__ __launch_bounds__(256)
void dilate_attn_kernel(const float* __restrict__ q,
                        const float* __restrict__ k,
                        const float* __restrict__ v,
                        float* __restrict__ out)
{
    int idx = blockIdx.x * blockDim.x + threadIdx.x;
    if (idx >= BD * HEADS * HW) return;

    int x    = idx % WD;
    int y    = (idx / WD) % HT;
    int head = (idx / HW) % HEADS;
    int b    = idx / (HW * HEADS);

    // base offset of channel 0 of this head in q/k/v
    int base = (b * CTOT + head * HD) * HW;
    int pix  = y * WD + x;

    // load q vector (strided by HW across channels; coalesced across warp lanes)
    float qv[HD];
    const float* qp = q + base + pix;
#pragma unroll
    for (int c = 0; c < HD; c++) qv[c] = qp[c * HW];

    const float scale = 0.17677669529663687f;  // 32^-0.5

    // ---- logits ----
    float attn[9];
#pragma unroll
    for (int p = 0; p < 9; p++) {
        int dy = (p / 3) * 2 - 2;
        int dx = (p % 3) * 2 - 2;
        int yy = y + dy;
        int xx = x + dx;
        float s = 0.0f;
        if ((unsigned)yy < (unsigned)HT && (unsigned)xx < (unsigned)WD) {
            const float* kp = k + base + yy * WD + xx;
            float acc = 0.0f;
#pragma unroll
            for (int c = 0; c < HD; c++) acc = fmaf(qv[c], kp[c * HW], acc);
            s = acc * scale;
        }
        attn[p] = s;  // OOB -> logit 0 (matches zero-padded unfold)
    }

    // ---- softmax over 9 ----
    float m = attn[0];
#pragma unroll
    for (int p = 1; p < 9; p++) m = fmaxf(m, attn[p]);
    float denom = 0.0f;
#pragma unroll
    for (int p = 0; p < 9; p++) {
        attn[p] = __expf(attn[p] - m);
        denom += attn[p];
    }
    float inv = 1.0f / denom;

    // ---- weighted sum of v ----
    float acc[HD];
#pragma unroll
    for (int c = 0; c < HD; c++) acc[c] = 0.0f;
#pragma unroll
    for (int p = 0; p < 9; p++) {
        int dy = (p / 3) * 2 - 2;
        int dx = (p % 3) * 2 - 2;
        int yy = y + dy;
        int xx = x + dx;
        if ((unsigned)yy < (unsigned)HT && (unsigned)xx < (unsigned)WD) {
            float w = attn[p];
            const float* vp = v + base + yy * WD + xx;
#pragma unroll
            for (int c = 0; c < HD; c++) acc[c] = fmaf(w, vp[c * HW], acc[c]);
        }
    }

    // ---- write out: out[b, y, x, head*32 + c] — 128 contiguous bytes/thread ----
    float4* o = (float4*)(out + (size_t)((b * HT + y) * WD + x) * CTOT + head * HD);
#pragma unroll
    for (int c = 0; c < HD; c += 4) {
        o[c / 4] = make_float4(acc[c] * inv, acc[c + 1] * inv,
                               acc[c + 2] * inv, acc[c + 3] * inv);
    }
}

extern "C" void kernel_launch(void* const* d_in, const int* in_sizes, int n_in,
                              void* d_out, int out_size)
{
    const float* q = (const float*)d_in[0];
    const float* k = (const float*)d_in[1];
    const float* v = (const float*)d_in[2];
    float* out = (float*)d_out;

    int total = BD * HEADS * HW;
    int threads = 256;
    int blocks = (total + threads - 1) / threads;
    dilate_attn_kernel<<<blocks, threads>>>(q, k, v, out);
}